// round 10
// baseline (speedup 1.0000x reference)
#include <cuda_runtime.h>
#include <cuda_bf16.h>

#define SS   8
#define HH   544
#define WW   960
#define HID  64
#define BT   256

__device__ __forceinline__ float fast_tanh(float x)
{
    float r;
    asm("tanh.approx.f32 %0, %1;" : "=f"(r) : "f"(x));
    return r;
}

__global__ __launch_bounds__(BT, 6)
void sky_kernel(const float* __restrict__ images,
                const float* __restrict__ extr,
                const float* __restrict__ intr,
                const float* __restrict__ W1,
                const float* __restrict__ b1,
                const float* __restrict__ W2,
                const float* __restrict__ b2,
                const float* __restrict__ pcd,
                const float* __restrict__ lsc,
                const int*   __restrict__ dsp,
                float* __restrict__ out, int N, int NW, int PERM)
{
    __shared__ float  sE[SS * 12];
    __shared__ float  sK[SS * 9];
    __shared__ float4 sW14[HID];   // {W1[0][j], W1[1][j], W1[2][j], b1[j]}
    __shared__ float4 sW24[HID];   // {W2[j][0], W2[j][1], W2[j][2], 0}
    __shared__ float  sB2[3];

    const int tid = threadIdx.x;

    float ds;
    {
        int iv = *dsp;
        ds = (iv > 0 && iv < 1000000) ? (float)iv : __int_as_float(iv);
    }

    if (tid < SS * 12) sE[tid] = extr[(tid / 12) * 16 + (tid % 12)];
    if (tid < SS * 9) {
        int ij = tid % 9, i = ij / 3, j = ij % 3;
        float d = 1.0f;
        if (i == 0 && (j == 0 || j == 2)) d = ds;
        if (i == 1 && (j == 1 || j == 2)) d = ds;
        sK[tid] = intr[tid] / d;
    }
    if (tid < HID) {
        sW14[tid] = make_float4(W1[tid], W1[HID + tid], W1[2 * HID + tid], b1[tid]);
        sW24[tid] = make_float4(W2[tid * 6 + 0], W2[tid * 6 + 1], W2[tid * 6 + 2], 0.f);
    }
    if (tid < 3) sB2[tid] = b2[tid];
    __syncthreads();

    // warp-granularity scatter (load balance across SMs)
    const int gwarp = (blockIdx.x * BT + tid) >> 5;
    if (gwarp >= NW) return;
    const long long pw = ((long long)gwarp * PERM) % NW;
    const int n = (int)(pw << 5) + (tid & 31);
    if (n >= N) return;

    const float X = pcd[3 * n + 0];
    const float Y = pcd[3 * n + 1];
    const float Z = pcd[3 * n + 2];

    float f0 = 0.f, f1 = 0.f, f2 = 0.f, cnt = 0.f;

    #pragma unroll
    for (int s = 0; s < SS; ++s) {
        const float* E = sE + s * 12;
        const float* K = sK + s * 9;
        float c0 = E[0] * X + E[1]  * Y + E[2]  * Z + E[3];
        float c1 = E[4] * X + E[5]  * Y + E[6]  * Z + E[7];
        float c2 = E[8] * X + E[9]  * Y + E[10] * Z + E[11];
        float u = K[0] * c0 + K[1] * c1 + K[2] * c2;
        float v = K[3] * c0 + K[4] * c1 + K[5] * c2;
        float w = K[6] * c0 + K[7] * c1 + K[8] * c2;
        float zs = (fabsf(w) > 1e-6f) ? w : 1e-6f;
        float px = u / zs;
        float py = v / zs;
        bool m = (w > 0.001f) && (px >= 0.f) && (px <= (float)(WW - 1)) &&
                 (py >= 0.f) && (py <= (float)(HH - 1));
        if (m) {
            int x0 = (int)floorf(px); x0 = min(max(x0, 0), WW - 2);
            int y0 = (int)floorf(py); y0 = min(max(y0, 0), HH - 2);
            float wx = px - (float)x0;
            float wy = py - (float)y0;
            float w00 = (1.f - wx) * (1.f - wy);
            float w01 = wx * (1.f - wy);
            float w10 = (1.f - wx) * wy;
            float w11 = wx * wy;
            const float* img = images + (size_t)s * 3 * HH * WW + (size_t)y0 * WW + x0;
            {
                const float* p = img;
                f0 += p[0] * w00 + p[1] * w01 + p[WW] * w10 + p[WW + 1] * w11;
            }
            {
                const float* p = img + (size_t)HH * WW;
                f1 += p[0] * w00 + p[1] * w01 + p[WW] * w10 + p[WW + 1] * w11;
            }
            {
                const float* p = img + (size_t)2 * HH * WW;
                f2 += p[0] * w00 + p[1] * w01 + p[WW] * w10 + p[WW + 1] * w11;
            }
            cnt += 1.f;
        }
    }

    float2* op = (float2*)(out + (size_t)6 * n);   // 24B offset -> 8B aligned

    if (cnt == 0.f) {
        op[0] = make_float2(0.f, 0.f);
        op[1] = make_float2(0.f, 0.f);
        op[2] = make_float2(0.f, 0.f);
        return;
    }

    const float inv = 1.f / cnt;
    f0 *= inv; f1 *= inv; f2 *= inv;

    float a0 = sB2[0], a1 = sB2[1], a2 = sB2[2];
    #pragma unroll
    for (int j = 0; j < HID; ++j) {
        const float4 wa = sW14[j];
        const float4 wb = sW24[j];
        float h = fmaf(f2, wa.z, fmaf(f1, wa.y, fmaf(f0, wa.x, wa.w)));
        h = fmaxf(h, 0.f);
        a0 = fmaf(h, wb.x, a0);
        a1 = fmaf(h, wb.y, a1);
        a2 = fmaf(h, wb.z, a2);
    }

    op[0] = make_float2(fast_tanh(a0), fast_tanh(a1));
    op[1] = make_float2(fast_tanh(a2), __expf(lsc[3 * n + 0]));
    op[2] = make_float2(__expf(lsc[3 * n + 1]), __expf(lsc[3 * n + 2]));
}

extern "C" void kernel_launch(void* const* d_in, const int* in_sizes, int n_in,
                              void* d_out, int out_size)
{
    const float* images = (const float*)d_in[0];
    const float* extr   = (const float*)d_in[1];
    const float* intr   = (const float*)d_in[2];
    const float* W1     = (const float*)d_in[3];
    const float* b1     = (const float*)d_in[4];
    const float* W2     = (const float*)d_in[5];
    const float* b2     = (const float*)d_in[6];
    const float* pcd    = (const float*)d_in[7];
    const float* lsc    = (const float*)d_in[8];
    const int*   dsp    = (const int*)  d_in[9];

    int N  = in_sizes[7] / 3;
    int NW = (N + 31) / 32;

    int PERM = (int)(0.6180339887 * NW) | 1;
    while (true) {
        int a = PERM, b = NW;
        while (b) { int t = a % b; a = b; b = t; }
        if (a == 1) break;
        PERM += 2;
    }

    int blocks = (NW * 32 + BT - 1) / BT;
    sky_kernel<<<blocks, BT>>>(images, extr, intr, W1, b1, W2, b2,
                               pcd, lsc, dsp, (float*)d_out, N, NW, PERM);
}

// round 11
// speedup vs baseline: 1.9044x; 1.9044x over previous
#include <cuda_runtime.h>
#include <cuda_bf16.h>

#define SS   8
#define HH   544
#define WW   960
#define HID  64
#define BT   256

__device__ __forceinline__ float fast_tanh(float x)
{
    float r;
    asm("tanh.approx.f32 %0, %1;" : "=f"(r) : "f"(x));
    return r;
}

__global__ __launch_bounds__(BT)
void sky_kernel(const float* __restrict__ images,
                const float* __restrict__ extr,
                const float* __restrict__ intr,
                const float* __restrict__ W1,
                const float* __restrict__ b1,
                const float* __restrict__ W2,
                const float* __restrict__ b2,
                const float* __restrict__ pcd,
                const float* __restrict__ lsc,
                const int*   __restrict__ dsp,
                float* __restrict__ out, int N, int NW, int PERM)
{
    __shared__ float  sE[SS * 12];
    __shared__ float  sK[SS * 9];
    __shared__ float4 sW14[HID];   // {W1[0][j], W1[1][j], W1[2][j], b1[j]}
    __shared__ float4 sW24[HID];   // {W2[j][0], W2[j][1], W2[j][2], 0}
    __shared__ float  sB2[3];

    const int tid = threadIdx.x;

    float ds;
    {
        int iv = *dsp;
        ds = (iv > 0 && iv < 1000000) ? (float)iv : __int_as_float(iv);
    }

    if (tid < SS * 12) sE[tid] = extr[(tid / 12) * 16 + (tid % 12)];
    if (tid < SS * 9) {
        int ij = tid % 9, i = ij / 3, j = ij % 3;
        float d = 1.0f;
        if (i == 0 && (j == 0 || j == 2)) d = ds;
        if (i == 1 && (j == 1 || j == 2)) d = ds;
        sK[tid] = intr[tid] / d;
    }
    if (tid < HID) {
        sW14[tid] = make_float4(W1[tid], W1[HID + tid], W1[2 * HID + tid], b1[tid]);
        sW24[tid] = make_float4(W2[tid * 6 + 0], W2[tid * 6 + 1], W2[tid * 6 + 2], 0.f);
    }
    if (tid < 3) sB2[tid] = b2[tid];
    __syncthreads();

    // warp-granularity scatter (load balance across SMs)
    const int gwarp = (blockIdx.x * BT + tid) >> 5;
    if (gwarp >= NW) return;
    const long long pw = ((long long)gwarp * PERM) % NW;
    const int n = (int)(pw << 5) + (tid & 31);
    if (n >= N) return;

    const float X = pcd[3 * n + 0];
    const float Y = pcd[3 * n + 1];
    const float Z = pcd[3 * n + 2];

    float f0 = 0.f, f1 = 0.f, f2 = 0.f, cnt = 0.f;

    #pragma unroll
    for (int s = 0; s < SS; ++s) {
        const float* E = sE + s * 12;
        const float* K = sK + s * 9;
        float c0 = E[0] * X + E[1]  * Y + E[2]  * Z + E[3];
        float c1 = E[4] * X + E[5]  * Y + E[6]  * Z + E[7];
        float c2 = E[8] * X + E[9]  * Y + E[10] * Z + E[11];
        float u = K[0] * c0 + K[1] * c1 + K[2] * c2;
        float v = K[3] * c0 + K[4] * c1 + K[5] * c2;
        float w = K[6] * c0 + K[7] * c1 + K[8] * c2;
        float zs = (fabsf(w) > 1e-6f) ? w : 1e-6f;
        float px = u / zs;
        float py = v / zs;
        bool m = (w > 0.001f) && (px >= 0.f) && (px <= (float)(WW - 1)) &&
                 (py >= 0.f) && (py <= (float)(HH - 1));
        if (m) {
            int x0 = (int)floorf(px); x0 = min(max(x0, 0), WW - 2);
            int y0 = (int)floorf(py); y0 = min(max(y0, 0), HH - 2);
            float wx = px - (float)x0;
            float wy = py - (float)y0;
            float w00 = (1.f - wx) * (1.f - wy);
            float w01 = wx * (1.f - wy);
            float w10 = (1.f - wx) * wy;
            float w11 = wx * wy;
            const float* img = images + (size_t)s * 3 * HH * WW + (size_t)y0 * WW + x0;
            {
                const float* p = img;
                f0 += p[0] * w00 + p[1] * w01 + p[WW] * w10 + p[WW + 1] * w11;
            }
            {
                const float* p = img + (size_t)HH * WW;
                f1 += p[0] * w00 + p[1] * w01 + p[WW] * w10 + p[WW + 1] * w11;
            }
            {
                const float* p = img + (size_t)2 * HH * WW;
                f2 += p[0] * w00 + p[1] * w01 + p[WW] * w10 + p[WW + 1] * w11;
            }
            cnt += 1.f;
        }
    }

    float2* op = (float2*)(out + (size_t)6 * n);   // 24B offset -> 8B aligned

    if (cnt == 0.f) {
        op[0] = make_float2(0.f, 0.f);
        op[1] = make_float2(0.f, 0.f);
        op[2] = make_float2(0.f, 0.f);
        return;
    }

    const float inv = 1.f / cnt;
    f0 *= inv; f1 *= inv; f2 *= inv;

    float a0 = sB2[0], a1 = sB2[1], a2 = sB2[2];
    #pragma unroll
    for (int j = 0; j < HID; ++j) {
        const float4 wa = sW14[j];
        const float4 wb = sW24[j];
        float h = fmaf(f2, wa.z, fmaf(f1, wa.y, fmaf(f0, wa.x, wa.w)));
        h = fmaxf(h, 0.f);
        a0 = fmaf(h, wb.x, a0);
        a1 = fmaf(h, wb.y, a1);
        a2 = fmaf(h, wb.z, a2);
    }

    op[0] = make_float2(fast_tanh(a0), fast_tanh(a1));
    op[1] = make_float2(fast_tanh(a2), __expf(lsc[3 * n + 0]));
    op[2] = make_float2(__expf(lsc[3 * n + 1]), __expf(lsc[3 * n + 2]));
}

extern "C" void kernel_launch(void* const* d_in, const int* in_sizes, int n_in,
                              void* d_out, int out_size)
{
    const float* images = (const float*)d_in[0];
    const float* extr   = (const float*)d_in[1];
    const float* intr   = (const float*)d_in[2];
    const float* W1     = (const float*)d_in[3];
    const float* b1     = (const float*)d_in[4];
    const float* W2     = (const float*)d_in[5];
    const float* b2     = (const float*)d_in[6];
    const float* pcd    = (const float*)d_in[7];
    const float* lsc    = (const float*)d_in[8];
    const int*   dsp    = (const int*)  d_in[9];

    int N  = in_sizes[7] / 3;
    int NW = (N + 31) / 32;

    int PERM = (int)(0.6180339887 * NW) | 1;
    while (true) {
        int a = PERM, b = NW;
        while (b) { int t = a % b; a = b; b = t; }
        if (a == 1) break;
        PERM += 2;
    }

    int blocks = (NW * 32 + BT - 1) / BT;
    sky_kernel<<<blocks, BT>>>(images, extr, intr, W1, b1, W2, b2,
                               pcd, lsc, dsp, (float*)d_out, N, NW, PERM);
}

// round 13
// speedup vs baseline: 1.9189x; 1.0076x over previous
#include <cuda_runtime.h>
#include <cuda_bf16.h>

#define SS   8
#define HH   544
#define WW   960
#define HID  64
#define BT   256
#define FULL 0xffffffffu
#define MAXN 400000

__device__ int g_vis_idx[MAXN];
__device__ int g_vis_cnt;

__global__ void zero_cnt_kernel() { g_vis_cnt = 0; }

__device__ __forceinline__ float fast_tanh(float x)
{
    float r;
    asm("tanh.approx.f32 %0, %1;" : "=f"(r) : "f"(x));
    return r;
}

__device__ __forceinline__ float decode_ds(const int* dsp)
{
    int iv = *dsp;
    return (iv > 0 && iv < 1000000) ? (float)iv : __int_as_float(iv);
}

// ---------------- Pass 1: visibility mask, zero-fill invisible, compact ids ----------------
__global__ __launch_bounds__(BT)
void pass1_kernel(const float* __restrict__ extr,
                  const float* __restrict__ intr,
                  const float* __restrict__ pcd,
                  const int*   __restrict__ dsp,
                  float* __restrict__ out, int N)
{
    __shared__ float sE[SS * 12];
    __shared__ float sK[SS * 9];
    __shared__ int   wOff[BT / 32];
    __shared__ int   blockBase;

    const int tid  = threadIdx.x;
    const int lane = tid & 31;
    const int wid  = tid >> 5;

    const float ds = decode_ds(dsp);
    if (tid < SS * 12) sE[tid] = extr[(tid / 12) * 16 + (tid % 12)];
    if (tid < SS * 9) {
        int ij = tid % 9, i = ij / 3, j = ij % 3;
        float d = 1.0f;
        if (i == 0 && (j == 0 || j == 2)) d = ds;
        if (i == 1 && (j == 1 || j == 2)) d = ds;
        sK[tid] = intr[tid] / d;
    }
    __syncthreads();

    const int n = blockIdx.x * BT + tid;
    const bool pvalid = (n < N);

    int mask = 0;
    if (pvalid) {
        const float X = pcd[3 * n + 0];
        const float Y = pcd[3 * n + 1];
        const float Z = pcd[3 * n + 2];
        #pragma unroll
        for (int s = 0; s < SS; ++s) {
            const float* E = sE + s * 12;
            const float* K = sK + s * 9;
            float c0 = E[0] * X + E[1]  * Y + E[2]  * Z + E[3];
            float c1 = E[4] * X + E[5]  * Y + E[6]  * Z + E[7];
            float c2 = E[8] * X + E[9]  * Y + E[10] * Z + E[11];
            float u = K[0] * c0 + K[1] * c1 + K[2] * c2;
            float v = K[3] * c0 + K[4] * c1 + K[5] * c2;
            float w = K[6] * c0 + K[7] * c1 + K[8] * c2;
            float zs = (fabsf(w) > 1e-6f) ? w : 1e-6f;
            float px = u / zs;
            float py = v / zs;
            bool m = (w > 0.001f) && (px >= 0.f) && (px <= (float)(WW - 1)) &&
                     (py >= 0.f) && (py <= (float)(HH - 1));
            if (m) mask |= (1 << s);
        }
    }
    const bool visible = (mask != 0);

    if (pvalid && !visible) {
        float2* op = (float2*)(out + (size_t)6 * n);
        op[0] = make_float2(0.f, 0.f);
        op[1] = make_float2(0.f, 0.f);
        op[2] = make_float2(0.f, 0.f);
    }

    // block-level compaction of visible point ids (one global atomic per block)
    const unsigned bal = __ballot_sync(FULL, visible);
    const int rank = __popc(bal & ((1u << lane) - 1u));
    if (lane == 0) wOff[wid] = __popc(bal);
    __syncthreads();
    if (tid == 0) {
        int run = 0;
        #pragma unroll
        for (int k = 0; k < BT / 32; ++k) { int c = wOff[k]; wOff[k] = run; run += c; }
        blockBase = run ? atomicAdd(&g_vis_cnt, run) : 0;
    }
    __syncthreads();
    if (visible) {
        int slot = blockBase + wOff[wid] + rank;
        if (slot < MAXN) g_vis_idx[slot] = n;
    }
}

// ---------------- Pass 2: full compute for visible points only ----------------
__global__ __launch_bounds__(BT)
void pass2_kernel(const float* __restrict__ images,
                  const float* __restrict__ extr,
                  const float* __restrict__ intr,
                  const float* __restrict__ W1,
                  const float* __restrict__ b1,
                  const float* __restrict__ W2,
                  const float* __restrict__ b2,
                  const float* __restrict__ pcd,
                  const float* __restrict__ lsc,
                  const int*   __restrict__ dsp,
                  float* __restrict__ out)
{
    const int cnt = g_vis_cnt;
    if (blockIdx.x * BT >= cnt) return;   // uniform early-exit for empty blocks

    __shared__ float sE[SS * 12];
    __shared__ float sK[SS * 9];
    __shared__ float sW1[3 * HID];
    __shared__ float sB1[HID];
    __shared__ float sW2[HID * 3];
    __shared__ float sB2[3];

    const int tid = threadIdx.x;

    const float ds = decode_ds(dsp);
    if (tid < SS * 12) sE[tid] = extr[(tid / 12) * 16 + (tid % 12)];
    if (tid < SS * 9) {
        int ij = tid % 9, i = ij / 3, j = ij % 3;
        float d = 1.0f;
        if (i == 0 && (j == 0 || j == 2)) d = ds;
        if (i == 1 && (j == 1 || j == 2)) d = ds;
        sK[tid] = intr[tid] / d;
    }
    if (tid < 3 * HID) sW1[tid] = W1[tid];
    if (tid < HID)     sB1[tid] = b1[tid];
    if (tid < HID * 3) sW2[tid] = W2[(tid / 3) * 6 + (tid % 3)];
    if (tid < 3)       sB2[tid] = b2[tid];
    __syncthreads();

    const int i = blockIdx.x * BT + tid;
    if (i >= cnt) return;
    const int n = g_vis_idx[i];

    const float X = pcd[3 * n + 0];
    const float Y = pcd[3 * n + 1];
    const float Z = pcd[3 * n + 2];

    float f0 = 0.f, f1 = 0.f, f2 = 0.f, cntc = 0.f;

    #pragma unroll
    for (int s = 0; s < SS; ++s) {
        const float* E = sE + s * 12;
        const float* K = sK + s * 9;
        float c0 = E[0] * X + E[1]  * Y + E[2]  * Z + E[3];
        float c1 = E[4] * X + E[5]  * Y + E[6]  * Z + E[7];
        float c2 = E[8] * X + E[9]  * Y + E[10] * Z + E[11];
        float u = K[0] * c0 + K[1] * c1 + K[2] * c2;
        float v = K[3] * c0 + K[4] * c1 + K[5] * c2;
        float w = K[6] * c0 + K[7] * c1 + K[8] * c2;
        float zs = (fabsf(w) > 1e-6f) ? w : 1e-6f;
        float px = u / zs;
        float py = v / zs;
        bool m = (w > 0.001f) && (px >= 0.f) && (px <= (float)(WW - 1)) &&
                 (py >= 0.f) && (py <= (float)(HH - 1));
        if (m) {
            int x0 = (int)floorf(px); x0 = min(max(x0, 0), WW - 2);
            int y0 = (int)floorf(py); y0 = min(max(y0, 0), HH - 2);
            float wx = px - (float)x0;
            float wy = py - (float)y0;
            float w00 = (1.f - wx) * (1.f - wy);
            float w01 = wx * (1.f - wy);
            float w10 = (1.f - wx) * wy;
            float w11 = wx * wy;
            const float* img = images + (size_t)s * 3 * HH * WW + (size_t)y0 * WW + x0;
            {
                const float* p = img;
                f0 += p[0] * w00 + p[1] * w01 + p[WW] * w10 + p[WW + 1] * w11;
            }
            {
                const float* p = img + (size_t)HH * WW;
                f1 += p[0] * w00 + p[1] * w01 + p[WW] * w10 + p[WW + 1] * w11;
            }
            {
                const float* p = img + (size_t)2 * HH * WW;
                f2 += p[0] * w00 + p[1] * w01 + p[WW] * w10 + p[WW + 1] * w11;
            }
            cntc += 1.f;
        }
    }

    const float inv = 1.f / fmaxf(cntc, 1.f);
    f0 *= inv; f1 *= inv; f2 *= inv;

    float a0 = sB2[0], a1 = sB2[1], a2 = sB2[2];
    #pragma unroll
    for (int j = 0; j < HID; ++j) {
        float h = f0 * sW1[j] + f1 * sW1[HID + j] + f2 * sW1[2 * HID + j] + sB1[j];
        h = fmaxf(h, 0.f);
        a0 = fmaf(h, sW2[j * 3 + 0], a0);
        a1 = fmaf(h, sW2[j * 3 + 1], a1);
        a2 = fmaf(h, sW2[j * 3 + 2], a2);
    }

    float2* op = (float2*)(out + (size_t)6 * n);
    op[0] = make_float2(fast_tanh(a0), fast_tanh(a1));
    op[1] = make_float2(fast_tanh(a2), __expf(lsc[3 * n + 0]));
    op[2] = make_float2(__expf(lsc[3 * n + 1]), __expf(lsc[3 * n + 2]));
}

extern "C" void kernel_launch(void* const* d_in, const int* in_sizes, int n_in,
                              void* d_out, int out_size)
{
    const float* images = (const float*)d_in[0];
    const float* extr   = (const float*)d_in[1];
    const float* intr   = (const float*)d_in[2];
    const float* W1     = (const float*)d_in[3];
    const float* b1     = (const float*)d_in[4];
    const float* W2     = (const float*)d_in[5];
    const float* b2     = (const float*)d_in[6];
    const float* pcd    = (const float*)d_in[7];
    const float* lsc    = (const float*)d_in[8];
    const int*   dsp    = (const int*)  d_in[9];

    int N = in_sizes[7] / 3;
    int blocks = (N + BT - 1) / BT;

    zero_cnt_kernel<<<1, 1>>>();
    pass1_kernel<<<blocks, BT>>>(extr, intr, pcd, dsp, (float*)d_out, N);
    pass2_kernel<<<blocks, BT>>>(images, extr, intr, W1, b1, W2, b2,
                                 pcd, lsc, dsp, (float*)d_out);
}

// round 14
// speedup vs baseline: 2.6083x; 1.3593x over previous
#include <cuda_runtime.h>
#include <cuda_bf16.h>

#define SS   8
#define HH   544
#define WW   960
#define HID  64
#define BT   256

typedef unsigned long long u64;

__device__ __forceinline__ float fast_tanh(float x)
{
    float r;
    asm("tanh.approx.f32 %0, %1;" : "=f"(r) : "f"(x));
    return r;
}

__device__ __forceinline__ u64 pk2(float lo, float hi)
{
    u64 r;
    asm("mov.b64 %0, {%1, %2};" : "=l"(r) : "f"(lo), "f"(hi));
    return r;
}

__device__ __forceinline__ void upk2(u64 v, float& lo, float& hi)
{
    asm("mov.b64 {%0, %1}, %2;" : "=f"(lo), "=f"(hi) : "l"(v));
}

__device__ __forceinline__ u64 fma2(u64 a, u64 b, u64 c)
{
    u64 r;
    asm("fma.rn.f32x2 %0, %1, %2, %3;" : "=l"(r) : "l"(a), "l"(b), "l"(c));
    return r;
}

__global__ __launch_bounds__(BT)
void sky_kernel(const float* __restrict__ images,
                const float* __restrict__ extr,
                const float* __restrict__ intr,
                const float* __restrict__ W1,
                const float* __restrict__ b1,
                const float* __restrict__ W2,
                const float* __restrict__ b2,
                const float* __restrict__ pcd,
                const float* __restrict__ lsc,
                const int*   __restrict__ dsp,
                float* __restrict__ out, int N, int NW, int PERM)
{
    __shared__ float sE[SS * 12];
    __shared__ float sK[SS * 9];
    // packed MLP weights: pair of hidden units per 64-bit word
    __shared__ u64 sW1p0[HID / 2], sW1p1[HID / 2], sW1p2[HID / 2], sB1p[HID / 2];
    __shared__ u64 sW2p0[HID / 2], sW2p1[HID / 2], sW2p2[HID / 2];
    __shared__ float sB2[3];

    const int tid = threadIdx.x;

    float ds;
    {
        int iv = *dsp;
        ds = (iv > 0 && iv < 1000000) ? (float)iv : __int_as_float(iv);
    }

    if (tid < SS * 12) sE[tid] = extr[(tid / 12) * 16 + (tid % 12)];
    if (tid < SS * 9) {
        int ij = tid % 9, i = ij / 3, j = ij % 3;
        float d = 1.0f;
        if (i == 0 && (j == 0 || j == 2)) d = ds;
        if (i == 1 && (j == 1 || j == 2)) d = ds;
        sK[tid] = intr[tid] / d;
    }
    if (tid < HID / 2) {
        const int j0 = 2 * tid, j1 = 2 * tid + 1;
        sW1p0[tid] = pk2(W1[j0],           W1[j1]);
        sW1p1[tid] = pk2(W1[HID + j0],     W1[HID + j1]);
        sW1p2[tid] = pk2(W1[2 * HID + j0], W1[2 * HID + j1]);
        sB1p[tid]  = pk2(b1[j0],           b1[j1]);
        sW2p0[tid] = pk2(W2[j0 * 6 + 0],   W2[j1 * 6 + 0]);
        sW2p1[tid] = pk2(W2[j0 * 6 + 1],   W2[j1 * 6 + 1]);
        sW2p2[tid] = pk2(W2[j0 * 6 + 2],   W2[j1 * 6 + 2]);
    }
    if (tid < 3) sB2[tid] = b2[tid];
    __syncthreads();

    // warp-granularity scatter (load balance across SMs)
    const int gwarp = (blockIdx.x * BT + tid) >> 5;
    if (gwarp >= NW) return;
    const long long pw = ((long long)gwarp * PERM) % NW;
    const int n = (int)(pw << 5) + (tid & 31);
    if (n >= N) return;

    const float X = pcd[3 * n + 0];
    const float Y = pcd[3 * n + 1];
    const float Z = pcd[3 * n + 2];

    float f0 = 0.f, f1 = 0.f, f2 = 0.f, cnt = 0.f;

    #pragma unroll
    for (int s = 0; s < SS; ++s) {
        const float* E = sE + s * 12;
        const float* K = sK + s * 9;
        float c0 = E[0] * X + E[1]  * Y + E[2]  * Z + E[3];
        float c1 = E[4] * X + E[5]  * Y + E[6]  * Z + E[7];
        float c2 = E[8] * X + E[9]  * Y + E[10] * Z + E[11];
        float u = K[0] * c0 + K[1] * c1 + K[2] * c2;
        float v = K[3] * c0 + K[4] * c1 + K[5] * c2;
        float w = K[6] * c0 + K[7] * c1 + K[8] * c2;
        float zs = (fabsf(w) > 1e-6f) ? w : 1e-6f;
        float px = u / zs;
        float py = v / zs;
        bool m = (w > 0.001f) && (px >= 0.f) && (px <= (float)(WW - 1)) &&
                 (py >= 0.f) && (py <= (float)(HH - 1));
        if (m) {
            int x0 = (int)floorf(px); x0 = min(max(x0, 0), WW - 2);
            int y0 = (int)floorf(py); y0 = min(max(y0, 0), HH - 2);
            float wx = px - (float)x0;
            float wy = py - (float)y0;
            float w00 = (1.f - wx) * (1.f - wy);
            float w01 = wx * (1.f - wy);
            float w10 = (1.f - wx) * wy;
            float w11 = wx * wy;
            const float* img = images + (size_t)s * 3 * HH * WW + (size_t)y0 * WW + x0;
            {
                const float* p = img;
                f0 += p[0] * w00 + p[1] * w01 + p[WW] * w10 + p[WW + 1] * w11;
            }
            {
                const float* p = img + (size_t)HH * WW;
                f1 += p[0] * w00 + p[1] * w01 + p[WW] * w10 + p[WW + 1] * w11;
            }
            {
                const float* p = img + (size_t)2 * HH * WW;
                f2 += p[0] * w00 + p[1] * w01 + p[WW] * w10 + p[WW + 1] * w11;
            }
            cnt += 1.f;
        }
    }

    float2* op = (float2*)(out + (size_t)6 * n);   // 24B offset -> 8B aligned

    if (cnt == 0.f) {
        op[0] = make_float2(0.f, 0.f);
        op[1] = make_float2(0.f, 0.f);
        op[2] = make_float2(0.f, 0.f);
        return;
    }

    const float inv = 1.f / cnt;
    f0 *= inv; f1 *= inv; f2 *= inv;

    // ---- packed f32x2 MLP: 2 hidden units per issue slot ----
    const u64 f0p = pk2(f0, f0);
    const u64 f1p = pk2(f1, f1);
    const u64 f2p = pk2(f2, f2);
    u64 a0p = 0ull, a1p = 0ull, a2p = 0ull;   // pack(0,0)

    #pragma unroll 4
    for (int j = 0; j < HID / 2; ++j) {
        u64 h = fma2(f0p, sW1p0[j],
                 fma2(f1p, sW1p1[j],
                  fma2(f2p, sW1p2[j], sB1p[j])));
        float hl, hh;
        upk2(h, hl, hh);
        hl = fmaxf(hl, 0.f);
        hh = fmaxf(hh, 0.f);
        h = pk2(hl, hh);
        a0p = fma2(h, sW2p0[j], a0p);
        a1p = fma2(h, sW2p1[j], a1p);
        a2p = fma2(h, sW2p2[j], a2p);
    }

    float a0l, a0h, a1l, a1h, a2l, a2h;
    upk2(a0p, a0l, a0h);
    upk2(a1p, a1l, a1h);
    upk2(a2p, a2l, a2h);
    const float a0 = sB2[0] + a0l + a0h;
    const float a1 = sB2[1] + a1l + a1h;
    const float a2 = sB2[2] + a2l + a2h;

    op[0] = make_float2(fast_tanh(a0), fast_tanh(a1));
    op[1] = make_float2(fast_tanh(a2), __expf(lsc[3 * n + 0]));
    op[2] = make_float2(__expf(lsc[3 * n + 1]), __expf(lsc[3 * n + 2]));
}

extern "C" void kernel_launch(void* const* d_in, const int* in_sizes, int n_in,
                              void* d_out, int out_size)
{
    const float* images = (const float*)d_in[0];
    const float* extr   = (const float*)d_in[1];
    const float* intr   = (const float*)d_in[2];
    const float* W1     = (const float*)d_in[3];
    const float* b1     = (const float*)d_in[4];
    const float* W2     = (const float*)d_in[5];
    const float* b2     = (const float*)d_in[6];
    const float* pcd    = (const float*)d_in[7];
    const float* lsc    = (const float*)d_in[8];
    const int*   dsp    = (const int*)  d_in[9];

    int N  = in_sizes[7] / 3;
    int NW = (N + 31) / 32;

    int PERM = (int)(0.6180339887 * NW) | 1;
    while (true) {
        int a = PERM, b = NW;
        while (b) { int t = a % b; a = b; b = t; }
        if (a == 1) break;
        PERM += 2;
    }

    int blocks = (NW * 32 + BT - 1) / BT;
    sky_kernel<<<blocks, BT>>>(images, extr, intr, W1, b1, W2, b2,
                               pcd, lsc, dsp, (float*)d_out, N, NW, PERM);
}